// round 8
// baseline (speedup 1.0000x reference)
#include <cuda_runtime.h>

#define BATCH 256
#define NPTS  4096
#define DYN_SMEM (NPTS*16 + NPTS*4)

// ---------- fast double helpers: fp32 seed + 1 Newton step ----------
__device__ __forceinline__ double drecip(double x) {
  double y = (double)__fdividef(1.0f, (float)x);
  y = y * (2.0 - x * y);
  return y;
}
__device__ __forceinline__ double drsqrt(double x) {
  double y = (double)rsqrtf((float)x);
  y = y * (1.5 - 0.5 * x * y * y);
  return y;
}

__device__ __forceinline__ void inv3x3(const float* __restrict__ Km, float* __restrict__ out) {
  double a=Km[0], b=Km[1], c=Km[2], d=Km[3], e=Km[4], f=Km[5], g=Km[6], h=Km[7], i=Km[8];
  double det = a*(e*i - f*h) - b*(d*i - f*g) + c*(d*h - e*g);
  double inv = 1.0 / det;
  out[0]=(float)((e*i - f*h)*inv); out[1]=(float)((c*h - b*i)*inv); out[2]=(float)((b*f - c*e)*inv);
  out[3]=(float)((f*g - d*i)*inv); out[4]=(float)((a*i - c*g)*inv); out[5]=(float)((c*d - a*f)*inv);
  out[6]=(float)((d*h - e*g)*inv); out[7]=(float)((b*g - a*h)*inv); out[8]=(float)((a*e - b*d)*inv);
}

__device__ __forceinline__ double det3d(const double* R) {
  return R[0]*(R[4]*R[8]-R[5]*R[7]) - R[1]*(R[3]*R[8]-R[5]*R[6]) + R[2]*(R[3]*R[7]-R[4]*R[6]);
}

__device__ __forceinline__ int p2i(int a, int b) {
  int mn = a < b ? a : b, mx = a < b ? b : a;
  return mn*(5-mn)/2 + mx;   // (0,0)=0 (0,1)=1 (0,2)=2 (1,1)=3 (1,2)=4 (2,2)=5
}

template<int P, int Q>
__device__ __forceinline__ void rot3d(double g[3][3], double Qm[3][3]) {
  constexpr int K2 = 3 - P - Q;
  double apq = g[P][Q];
  double app = g[P][P], aqq = g[Q][Q];
  if (fabs(apq) <= 1e-15 * (fabs(app) + fabs(aqq))) return;
  double tau = (aqq - app) * drecip(2.0 * apq);
  double opt2 = 1.0 + tau*tau;
  double sq = opt2 * drsqrt(opt2);
  double tt = ((tau >= 0.0) ? 1.0 : -1.0) * drecip(fabs(tau) + sq);
  double c = drsqrt(1.0 + tt*tt);
  double s = tt * c;
  double akp = g[K2][P], akq = g[K2][Q];
  double np = c*akp - s*akq, nq = s*akp + c*akq;
  g[K2][P] = np; g[P][K2] = np;
  g[K2][Q] = nq; g[Q][K2] = nq;
  g[P][P] = app - tt*apq;
  g[Q][Q] = aqq + tt*apq;
  g[P][Q] = 0.0; g[Q][P] = 0.0;
  #pragma unroll
  for (int r = 0; r < 3; r++) {
    double qp = Qm[r][P], qq = Qm[r][Q];
    Qm[r][P] = c*qp - s*qq;
    Qm[r][Q] = s*qp + c*qq;
  }
}

// ---------- single fused kernel: one block per batch ----------
__global__ __launch_bounds__(256, 2) void k_fused(const float* __restrict__ kpts0,
                                                  const float* __restrict__ kpts1,
                                                  const float* __restrict__ conf,
                                                  const float* __restrict__ tscale,
                                                  const float* __restrict__ Kmat,
                                                  float* __restrict__ out) {
  const int b = blockIdx.x;
  const int tid = threadIdx.x;
  const int warp = tid >> 5, lane = tid & 31;

  extern __shared__ char dyn[];
  float4* sP = (float4*)dyn;                    // x00,x01,x10,x11 (affine path)
  float*  sW = (float*)(dyn + NPTS*16);         // w

  __shared__ float sKi[18];
  __shared__ float sred[8][36];
  __shared__ double sd[81];          // solver scratch: 2x81 floats, then 81 doubles
  __shared__ float sT[36];
  __shared__ float sR1[9], sR2[9], st3[3];
  __shared__ float scs[4], sss[4];
  __shared__ int sAffine;

  // ---- phase 0: K inverses ----
  if (tid == 0) {
    float ki0[9], ki1[9];
    inv3x3(Kmat + b*18, ki0);
    inv3x3(Kmat + b*18 + 9, ki1);
    #pragma unroll
    for (int i=0;i<9;i++) { sKi[i]=ki0[i]; sKi[9+i]=ki1[i]; }
    sAffine = (ki0[6]==0.f && ki0[7]==0.f && ki0[8]==1.f &&
               ki1[6]==0.f && ki1[7]==0.f && ki1[8]==1.f) ? 1 : 0;
  }
  __syncthreads();
  float Ki0[9], Ki1[9];
  #pragma unroll
  for (int i=0;i<9;i++){ Ki0[i]=sKi[i]; Ki1[i]=sKi[9+i]; }
  const int affine = sAffine;

  const float2* kp0 = (const float2*)(kpts0) + (size_t)b*NPTS;
  const float2* kp1 = (const float2*)(kpts1) + (size_t)b*NPTS;
  const float*  wv  = conf + (size_t)b*NPTS;

  // ---- phase 1: accumulate T[6][6] (tensor form of M) + stage coords ----
  {
    float acc[36];
    #pragma unroll
    for (int i=0;i<36;i++) acc[i]=0.f;

    float2 c0 = kp0[tid], c1 = kp1[tid];
    float  cw = wv[tid];
    #pragma unroll
    for (int k = 0; k < NPTS/256; k++) {
      float2 n0, n1; float nw;
      if (k < NPTS/256 - 1) {
        n0 = kp0[tid + (k+1)*256];
        n1 = kp1[tid + (k+1)*256];
        nw = wv[tid + (k+1)*256];
      }
      float x00 = Ki0[0]*c0.x + Ki0[1]*c0.y + Ki0[2];
      float x01 = Ki0[3]*c0.x + Ki0[4]*c0.y + Ki0[5];
      float x02 = Ki0[6]*c0.x + Ki0[7]*c0.y + Ki0[8];
      float x10 = Ki1[0]*c1.x + Ki1[1]*c1.y + Ki1[2];
      float x11 = Ki1[3]*c1.x + Ki1[4]*c1.y + Ki1[5];
      float x12 = Ki1[6]*c1.x + Ki1[7]*c1.y + Ki1[8];
      int n = tid + k*256;
      sP[n] = make_float4(x00, x01, x10, x11);
      sW[n] = cw;
      float s0[6] = {x00*x00, x00*x01, x00*x02, x01*x01, x01*x02, x02*x02};
      float s1[6] = {x10*x10, x10*x11, x10*x12, x11*x11, x11*x12, x12*x12};
      float ws1[6];
      #pragma unroll
      for (int a=0;a<6;a++) ws1[a] = cw*s1[a];
      #pragma unroll
      for (int a=0;a<6;a++)
        #pragma unroll
        for (int bb2=0;bb2<6;bb2++)
          acc[a*6+bb2] = fmaf(ws1[a], s0[bb2], acc[a*6+bb2]);
      c0 = n0; c1 = n1; cw = nw;
    }
    #pragma unroll
    for (int i=0;i<36;i++) {
      acc[i] += __shfl_down_sync(0xffffffffu, acc[i], 16);
      acc[i] += __shfl_down_sync(0xffffffffu, acc[i], 8);
      acc[i] += __shfl_down_sync(0xffffffffu, acc[i], 4);
      acc[i] += __shfl_down_sync(0xffffffffu, acc[i], 2);
      acc[i] += __shfl_down_sync(0xffffffffu, acc[i], 1);
    }
    if (lane == 0) {
      #pragma unroll
      for (int i=0;i<36;i++) sred[warp][i] = acc[i];
    }
    __syncthreads();
    if (tid < 36) {
      float s = 0.f;
      #pragma unroll
      for (int wp=0; wp<8; wp++) s += sred[wp][tid];
      sT[tid] = s;
    }
    __syncthreads();
  }

  // ---- phase 2: eigensolve + essential decomposition (warp 0 only) ----
  if (warp == 0) {
    float* A = (float*)&sd[0];
    float* V = ((float*)&sd[0]) + 81;

    if (lane < 9) {
      const int i0 = lane / 3, j0 = lane % 3;
      #pragma unroll
      for (int j = 0; j < 9; j++) {
        int k0 = j / 3, l0 = j % 3;
        A[lane*9+j] = sT[p2i(i0,k0)*6 + p2i(j0,l0)];
        V[lane*9+j] = (lane==j) ? 1.0f : 0.0f;
      }
    }
    __syncwarp();

    // Phase A: parallel-ordered fp32 Jacobi (4 disjoint rotations per step)
    for (int sweep = 0; sweep < 4; sweep++) {
      for (int r = 0; r < 9; r++) {
        const int bye = (5 * ((2*r) % 9)) % 9;
        if (lane < 4) {
          int d = lane + 1;
          int a = (bye + d) % 9;
          int bq = (bye + 9 - d) % 9;
          int p = a < bq ? a : bq;
          int q = a < bq ? bq : a;
          float apq = A[p*9+q], app = A[p*9+p], aqq = A[q*9+q];
          float c = 1.0f, s = 0.0f;
          if (fabsf(apq) > 6e-8f * (fabsf(app) + fabsf(aqq))) {
            float tau = __fdividef(aqq - app, 2.0f * apq);
            float t = ((tau >= 0.0f) ? 1.0f : -1.0f) / (fabsf(tau) + sqrtf(1.0f + tau*tau));
            c = rsqrtf(1.0f + t*t);
            s = t * c;
          }
          scs[lane] = c; sss[lane] = s;
        }
        __syncwarp();
        float cr[4], sr[4];
        int pr[4], qr[4];
        #pragma unroll
        for (int d = 0; d < 4; d++) {
          cr[d] = scs[d]; sr[d] = sss[d];
          int a = (bye + d + 1) % 9;
          int bq = (bye + 8 - d) % 9;
          pr[d] = a < bq ? a : bq;
          qr[d] = a < bq ? bq : a;
        }
        if (lane < 9) {
          #pragma unroll
          for (int d = 0; d < 4; d++) {
            int p = pr[d], q = qr[d];
            float vp = A[lane*9+p], vq = A[lane*9+q];
            A[lane*9+p] = cr[d]*vp - sr[d]*vq;
            A[lane*9+q] = sr[d]*vp + cr[d]*vq;
            float wp = V[lane*9+p], wq = V[lane*9+q];
            V[lane*9+p] = cr[d]*wp - sr[d]*wq;
            V[lane*9+q] = sr[d]*wp + cr[d]*wq;
          }
        }
        __syncwarp();
        if (lane < 9) {
          #pragma unroll
          for (int d = 0; d < 4; d++) {
            int p = pr[d], q = qr[d];
            float vp = A[p*9+lane], vq = A[q*9+lane];
            A[p*9+lane] = cr[d]*vp - sr[d]*vq;
            A[q*9+lane] = sr[d]*vp + cr[d]*vq;
          }
        }
        __syncwarp();
      }
    }

    if (lane == 0) {
      int mi = 0; float mv = A[0];
      #pragma unroll
      for (int k=1;k<9;k++){ float dv=A[k*9+k]; if (dv<mv){mv=dv;mi=k;} }
      double x[9];
      #pragma unroll
      for (int k=0;k<9;k++) x[k] = (double)V[k*9+mi];
      double sigma = (double)mv;

      // D = M - sigma*I from T
      double* D = &sd[0];
      for (int i=0;i<9;i++) {
        int i0 = i/3, j0 = i%3;
        for (int j=i;j<9;j++) {
          int k0 = j/3, l0 = j%3;
          double v = (double)sT[p2i(i0,k0)*6 + p2i(j0,l0)];
          D[i*9+j] = v; D[j*9+i] = v;
        }
      }
      for (int i=0;i<9;i++) D[i*9+i] -= sigma;

      // LU with partial pivoting
      int ipiv[9];
      double Dinv[9];
      for (int k=0;k<9;k++) {
        int p = k; double mx = fabs(D[k*9+k]);
        for (int i=k+1;i<9;i++){ double v = fabs(D[i*9+k]); if (v > mx){ mx=v; p=i; } }
        ipiv[k] = p;
        if (p != k)
          for (int j=0;j<9;j++){ double t=D[k*9+j]; D[k*9+j]=D[p*9+j]; D[p*9+j]=t; }
        double pv = D[k*9+k];
        if (fabs(pv) < 1e-30) pv = (pv >= 0.0) ? 1e-30 : -1e-30;
        double ipv = drecip(pv);
        Dinv[k] = ipv;
        for (int i=k+1;i<9;i++) {
          double l = D[i*9+k] * ipv;
          D[i*9+k] = l;
          for (int j=k+1;j<9;j++) D[i*9+j] -= l * D[k*9+j];
        }
      }
      // two inverse-iteration solves
      for (int it=0; it<2; it++) {
        for (int k=0;k<9;k++){ int p=ipiv[k]; if (p!=k){ double t=x[k]; x[k]=x[p]; x[p]=t; } }
        for (int i=1;i<9;i++){ double s=x[i]; for (int j=0;j<i;j++) s -= D[i*9+j]*x[j]; x[i]=s; }
        for (int i=8;i>=0;i--){ double s=x[i]; for (int j=i+1;j<9;j++) s -= D[i*9+j]*x[j]; x[i]=s*Dinv[i]; }
        double nn = 0.0;
        for (int k=0;k<9;k++) nn += x[k]*x[k];
        double innn = drsqrt(nn);
        for (int k=0;k<9;k++) x[k] *= innn;
      }

      double e[9];
      #pragma unroll
      for (int k=0;k<9;k++) e[k] = x[k];

      // 3x3 SVD of E via double Jacobi on E^T E (3 sweeps)
      double G3[3][3];
      #pragma unroll
      for (int i=0;i<3;i++)
        #pragma unroll
        for (int j=0;j<3;j++)
          G3[i][j] = e[0+i]*e[0+j] + e[3+i]*e[3+j] + e[6+i]*e[6+j];

      double Qm[3][3] = {{1,0,0},{0,1,0},{0,0,1}};
      #pragma unroll
      for (int sw=0; sw<3; sw++) { rot3d<0,1>(G3,Qm); rot3d<0,2>(G3,Qm); rot3d<1,2>(G3,Qm); }

      double lam0=G3[0][0], lam1=G3[1][1], lam2=G3[2][2];
      int o0, o1, o2;
      if (lam0 >= lam1) {
        if (lam0 >= lam2) { o0=0; if (lam1>=lam2){o1=1;o2=2;} else {o1=2;o2=1;} }
        else              { o0=2; o1=0; o2=1; }
      } else {
        if (lam1 >= lam2) { o0=1; if (lam0>=lam2){o1=0;o2=2;} else {o1=2;o2=0;} }
        else              { o0=2; o1=1; o2=0; }
      }
      double v1[3] = {Qm[0][o0], Qm[1][o0], Qm[2][o0]};
      double v2[3] = {Qm[0][o1], Qm[1][o1], Qm[2][o1]};
      double v3[3] = {Qm[0][o2], Qm[1][o2], Qm[2][o2]};

      double u1[3], u2[3], u3[3];
      #pragma unroll
      for (int i=0;i<3;i++) {
        u1[i] = e[3*i+0]*v1[0] + e[3*i+1]*v1[1] + e[3*i+2]*v1[2];
        u2[i] = e[3*i+0]*v2[0] + e[3*i+1]*v2[1] + e[3*i+2]*v2[2];
      }
      double in1 = drsqrt(fmax(u1[0]*u1[0]+u1[1]*u1[1]+u1[2]*u1[2], 1e-300));
      double in2 = drsqrt(fmax(u2[0]*u2[0]+u2[1]*u2[1]+u2[2]*u2[2], 1e-300));
      #pragma unroll
      for (int i=0;i<3;i++){ u1[i]*=in1; u2[i]*=in2; }
      u3[0] = u1[1]*u2[2] - u1[2]*u2[1];
      u3[1] = u1[2]*u2[0] - u1[0]*u2[2];
      u3[2] = u1[0]*u2[1] - u1[1]*u2[0];
      double in3 = drsqrt(fmax(u3[0]*u3[0]+u3[1]*u3[1]+u3[2]*u3[2], 1e-300));
      #pragma unroll
      for (int i=0;i<3;i++) u3[i]*=in3;

      double R1[9], R2[9];
      #pragma unroll
      for (int i=0;i<3;i++)
        #pragma unroll
        for (int j=0;j<3;j++) {
          R1[3*i+j] =  u2[i]*v1[j] - u1[i]*v2[j] + u3[i]*v3[j];
          R2[3*i+j] = -u2[i]*v1[j] + u1[i]*v2[j] + u3[i]*v3[j];
        }
      double d1 = det3d(R1);
      double d2 = det3d(R2);
      double s1 = (d1 > 0.0) ? 1.0 : ((d1 < 0.0) ? -1.0 : 0.0);
      double s2 = (d2 > 0.0) ? 1.0 : ((d2 < 0.0) ? -1.0 : 0.0);
      #pragma unroll
      for (int i=0;i<9;i++) {
        sR1[i] = (float)(R1[i]*s1);
        sR2[i] = (float)(R2[i]*s2);
      }
      #pragma unroll
      for (int i=0;i<3;i++) st3[i] = (float)u3[i];
    }
  }
  __syncthreads();

  // ---- phase 3: cheirality (division-free sign tests) ----
  float R1[9], R2[9];
  #pragma unroll
  for (int i=0;i<9;i++){ R1[i]=sR1[i]; R2[i]=sR2[i]; }
  const float tv0=st3[0], tv1=st3[1], tv2=st3[2];

  float sc0=0.f, sc1=0.f, sc2=0.f, sc3=0.f;
  if (affine) {
    #pragma unroll
    for (int k = 0; k < NPTS/256; k++) {
      int n = tid + k*256;
      float4 q = sP[n];
      float w = sW[n];
      // x02 = x12 = 1 on this path
      float bb = q.z*q.z + q.w*q.w + 1.0f;
      float bt = q.z*tv0 + q.w*tv1 + tv2;
      {
        float a0 = R1[0]*q.x + R1[1]*q.y + R1[2];
        float a1 = R1[3]*q.x + R1[4]*q.y + R1[5];
        float a2 = R1[6]*q.x + R1[7]*q.y + R1[8];
        float aa = a0*a0 + a1*a1 + a2*a2;
        float ab = a0*q.z + a1*q.w + a2;
        float at = a0*tv0 + a1*tv1 + a2*tv2;
        float det = aa*bb - ab*ab + 1e-9f;
        float n0 = -at*bb + ab*bt;
        float n1 = aa*bt - ab*at;
        bool dp = det >= 0.f;
        if (dp ? (n0 > 0.f && n1 > 0.f) : (n0 < 0.f && n1 < 0.f)) sc0 += w;
        if (dp ? (n0 < 0.f && n1 < 0.f) : (n0 > 0.f && n1 > 0.f)) sc1 += w;
      }
      {
        float a0 = R2[0]*q.x + R2[1]*q.y + R2[2];
        float a1 = R2[3]*q.x + R2[4]*q.y + R2[5];
        float a2 = R2[6]*q.x + R2[7]*q.y + R2[8];
        float aa = a0*a0 + a1*a1 + a2*a2;
        float ab = a0*q.z + a1*q.w + a2;
        float at = a0*tv0 + a1*tv1 + a2*tv2;
        float det = aa*bb - ab*ab + 1e-9f;
        float n0 = -at*bb + ab*bt;
        float n1 = aa*bt - ab*at;
        bool dp = det >= 0.f;
        if (dp ? (n0 > 0.f && n1 > 0.f) : (n0 < 0.f && n1 < 0.f)) sc2 += w;
        if (dp ? (n0 < 0.f && n1 < 0.f) : (n0 > 0.f && n1 > 0.f)) sc3 += w;
      }
    }
  } else {
    #pragma unroll
    for (int k = 0; k < NPTS/256; k++) {
      int n = tid + k*256;
      float2 p0 = kp0[n]; float2 p1 = kp1[n]; float w = wv[n];
      float x00 = Ki0[0]*p0.x + Ki0[1]*p0.y + Ki0[2];
      float x01 = Ki0[3]*p0.x + Ki0[4]*p0.y + Ki0[5];
      float x02 = Ki0[6]*p0.x + Ki0[7]*p0.y + Ki0[8];
      float x10 = Ki1[0]*p1.x + Ki1[1]*p1.y + Ki1[2];
      float x11 = Ki1[3]*p1.x + Ki1[4]*p1.y + Ki1[5];
      float x12 = Ki1[6]*p1.x + Ki1[7]*p1.y + Ki1[8];
      float bb = x10*x10 + x11*x11 + x12*x12;
      float bt = x10*tv0 + x11*tv1 + x12*tv2;
      {
        float a0 = R1[0]*x00 + R1[1]*x01 + R1[2]*x02;
        float a1 = R1[3]*x00 + R1[4]*x01 + R1[5]*x02;
        float a2 = R1[6]*x00 + R1[7]*x01 + R1[8]*x02;
        float aa = a0*a0 + a1*a1 + a2*a2;
        float ab = a0*x10 + a1*x11 + a2*x12;
        float at = a0*tv0 + a1*tv1 + a2*tv2;
        float det = aa*bb - ab*ab + 1e-9f;
        float n0 = -at*bb + ab*bt;
        float n1 = aa*bt - ab*at;
        bool dp = det >= 0.f;
        if (dp ? (n0 > 0.f && n1 > 0.f) : (n0 < 0.f && n1 < 0.f)) sc0 += w;
        if (dp ? (n0 < 0.f && n1 < 0.f) : (n0 > 0.f && n1 > 0.f)) sc1 += w;
      }
      {
        float a0 = R2[0]*x00 + R2[1]*x01 + R2[2]*x02;
        float a1 = R2[3]*x00 + R2[4]*x01 + R2[5]*x02;
        float a2 = R2[6]*x00 + R2[7]*x01 + R2[8]*x02;
        float aa = a0*a0 + a1*a1 + a2*a2;
        float ab = a0*x10 + a1*x11 + a2*x12;
        float at = a0*tv0 + a1*tv1 + a2*tv2;
        float det = aa*bb - ab*ab + 1e-9f;
        float n0 = -at*bb + ab*bt;
        float n1 = aa*bt - ab*at;
        bool dp = det >= 0.f;
        if (dp ? (n0 > 0.f && n1 > 0.f) : (n0 < 0.f && n1 < 0.f)) sc2 += w;
        if (dp ? (n0 < 0.f && n1 < 0.f) : (n0 > 0.f && n1 > 0.f)) sc3 += w;
      }
    }
  }
  #pragma unroll
  for (int off=16; off; off>>=1) {
    sc0 += __shfl_down_sync(0xffffffffu, sc0, off);
    sc1 += __shfl_down_sync(0xffffffffu, sc1, off);
    sc2 += __shfl_down_sync(0xffffffffu, sc2, off);
    sc3 += __shfl_down_sync(0xffffffffu, sc3, off);
  }
  if (lane == 0) { sred[warp][0]=sc0; sred[warp][1]=sc1; sred[warp][2]=sc2; sred[warp][3]=sc3; }
  __syncthreads();
  if (tid == 0) {
    float s0=0.f, s1=0.f, s2=0.f, s3=0.f;
    #pragma unroll
    for (int wp=0; wp<8; wp++){ s0+=sred[wp][0]; s1+=sred[wp][1]; s2+=sred[wp][2]; s3+=sred[wp][3]; }
    float bs = s0; int bi = 0;
    if (s1 > bs){ bs=s1; bi=1; }
    if (s2 > bs){ bs=s2; bi=2; }
    if (s3 > bs){ bs=s3; bi=3; }
    const float* R = (bi < 2) ? sR1 : sR2;
    float sgn = (bi & 1) ? -1.f : 1.f;
    float ts = tscale[b*2];
    float t0 = (sgn*st3[0])*ts;
    float t1 = (sgn*st3[1])*ts;
    float t2 = (sgn*st3[2])*ts;
    float* o = out + (size_t)b*32;
    o[0]=R[0]; o[1]=R[1]; o[2]=R[2];  o[3]=t0;
    o[4]=R[3]; o[5]=R[4]; o[6]=R[5];  o[7]=t1;
    o[8]=R[6]; o[9]=R[7]; o[10]=R[8]; o[11]=t2;
    o[12]=0.f; o[13]=0.f; o[14]=0.f; o[15]=1.f;
    float ti0 = -(R[0]*t0 + R[3]*t1 + R[6]*t2);
    float ti1 = -(R[1]*t0 + R[4]*t1 + R[7]*t2);
    float ti2 = -(R[2]*t0 + R[5]*t1 + R[8]*t2);
    o[16]=R[0]; o[17]=R[3]; o[18]=R[6]; o[19]=ti0;
    o[20]=R[1]; o[21]=R[4]; o[22]=R[7]; o[23]=ti1;
    o[24]=R[2]; o[25]=R[5]; o[26]=R[8]; o[27]=ti2;
    o[28]=0.f; o[29]=0.f; o[30]=0.f; o[31]=1.f;
  }
}

extern "C" void kernel_launch(void* const* d_in, const int* in_sizes, int n_in,
                              void* d_out, int out_size) {
  const float* kpts0  = (const float*)d_in[0];
  const float* kpts1  = (const float*)d_in[1];
  const float* conf   = (const float*)d_in[2];
  const float* tscale = (const float*)d_in[3];
  const float* Kmat   = (const float*)d_in[4];
  float* out = (float*)d_out;

  cudaFuncSetAttribute(k_fused, cudaFuncAttributeMaxDynamicSharedMemorySize, DYN_SMEM);
  k_fused<<<BATCH, 256, DYN_SMEM>>>(kpts0, kpts1, conf, tscale, Kmat, out);
}

// round 9
// speedup vs baseline: 1.1696x; 1.1696x over previous
#include <cuda_runtime.h>

#define BATCH 256
#define NPTS  4096
#define DYN_SMEM (NPTS*16 + NPTS*4)

// ---------- fast double helpers: fp32 seed + 1 Newton step ----------
__device__ __forceinline__ double drecip(double x) {
  double y = (double)__fdividef(1.0f, (float)x);
  y = y * (2.0 - x * y);
  return y;
}
__device__ __forceinline__ double drsqrt(double x) {
  double y = (double)rsqrtf((float)x);
  y = y * (1.5 - 0.5 * x * y * y);
  return y;
}

__device__ __forceinline__ void inv3x3(const float* __restrict__ Km, float* __restrict__ out) {
  double a=Km[0], b=Km[1], c=Km[2], d=Km[3], e=Km[4], f=Km[5], g=Km[6], h=Km[7], i=Km[8];
  double det = a*(e*i - f*h) - b*(d*i - f*g) + c*(d*h - e*g);
  double inv = 1.0 / det;
  out[0]=(float)((e*i - f*h)*inv); out[1]=(float)((c*h - b*i)*inv); out[2]=(float)((b*f - c*e)*inv);
  out[3]=(float)((f*g - d*i)*inv); out[4]=(float)((a*i - c*g)*inv); out[5]=(float)((c*d - a*f)*inv);
  out[6]=(float)((d*h - e*g)*inv); out[7]=(float)((b*g - a*h)*inv); out[8]=(float)((a*e - b*d)*inv);
}

__device__ __forceinline__ int p2i(int a, int b) {
  int mn = a < b ? a : b, mx = a < b ? b : a;
  return mn*(5-mn)/2 + mx;
}

template<int P, int Q>
__device__ __forceinline__ void rot3d(double g[3][3], double Qm[3][3]) {
  constexpr int K2 = 3 - P - Q;
  double apq = g[P][Q];
  double app = g[P][P], aqq = g[Q][Q];
  if (fabs(apq) <= 1e-15 * (fabs(app) + fabs(aqq))) return;
  double tau = (aqq - app) * drecip(2.0 * apq);
  double opt2 = 1.0 + tau*tau;
  double sq = opt2 * drsqrt(opt2);
  double tt = ((tau >= 0.0) ? 1.0 : -1.0) * drecip(fabs(tau) + sq);
  double c = drsqrt(1.0 + tt*tt);
  double s = tt * c;
  double akp = g[K2][P], akq = g[K2][Q];
  double np = c*akp - s*akq, nq = s*akp + c*akq;
  g[K2][P] = np; g[P][K2] = np;
  g[K2][Q] = nq; g[Q][K2] = nq;
  g[P][P] = app - tt*apq;
  g[Q][Q] = aqq + tt*apq;
  g[P][Q] = 0.0; g[Q][P] = 0.0;
  #pragma unroll
  for (int r = 0; r < 3; r++) {
    double qp = Qm[r][P], qq = Qm[r][Q];
    Qm[r][P] = c*qp - s*qq;
    Qm[r][Q] = s*qp + c*qq;
  }
}

// ---------- single fused kernel: one block per batch ----------
__global__ __launch_bounds__(256, 2) void k_fused(const float* __restrict__ kpts0,
                                                  const float* __restrict__ kpts1,
                                                  const float* __restrict__ conf,
                                                  const float* __restrict__ tscale,
                                                  const float* __restrict__ Kmat,
                                                  float* __restrict__ out) {
  const int b = blockIdx.x;
  const int tid = threadIdx.x;
  const int warp = tid >> 5, lane = tid & 31;

  extern __shared__ char dyn[];
  float4* sP = (float4*)dyn;
  float*  sW = (float*)(dyn + NPTS*16);

  __shared__ float sKi[18];
  __shared__ float sred[8][36];
  __shared__ double sd[81];           // A/V floats, then D doubles
  __shared__ float sT[36];
  __shared__ float sR1[9], sR2[9], st3[3];
  __shared__ float scs[4], sss[4];
  __shared__ double sx[9], sDinv[9], sUV[18], sSgn, sSigma;
  __shared__ int sIpiv[9], sMi;
  __shared__ int sAffine;

  // ---- phase 0: K inverses ----
  if (tid == 0) {
    float ki0[9], ki1[9];
    inv3x3(Kmat + b*18, ki0);
    inv3x3(Kmat + b*18 + 9, ki1);
    #pragma unroll
    for (int i=0;i<9;i++) { sKi[i]=ki0[i]; sKi[9+i]=ki1[i]; }
    sAffine = (ki0[6]==0.f && ki0[7]==0.f && ki0[8]==1.f &&
               ki1[6]==0.f && ki1[7]==0.f && ki1[8]==1.f) ? 1 : 0;
  }
  __syncthreads();
  float Ki0[9], Ki1[9];
  #pragma unroll
  for (int i=0;i<9;i++){ Ki0[i]=sKi[i]; Ki1[i]=sKi[9+i]; }
  const int affine = sAffine;

  const float2* kp0 = (const float2*)(kpts0) + (size_t)b*NPTS;
  const float2* kp1 = (const float2*)(kpts1) + (size_t)b*NPTS;
  const float*  wv  = conf + (size_t)b*NPTS;

  // ---- phase 1: accumulate T[6][6] + stage coords (prefetch depth 2) ----
  {
    float acc[36];
    #pragma unroll
    for (int i=0;i<36;i++) acc[i]=0.f;

    float2 c0 = kp0[tid],      c1 = kp1[tid];      float cw = wv[tid];
    float2 d0 = kp0[tid+256],  d1 = kp1[tid+256];  float dw = wv[tid+256];
    #pragma unroll
    for (int k = 0; k < NPTS/256; k++) {
      float2 n0, n1; float nw;
      if (k < NPTS/256 - 2) {
        n0 = kp0[tid + (k+2)*256];
        n1 = kp1[tid + (k+2)*256];
        nw = wv[tid + (k+2)*256];
      }
      float x00 = Ki0[0]*c0.x + Ki0[1]*c0.y + Ki0[2];
      float x01 = Ki0[3]*c0.x + Ki0[4]*c0.y + Ki0[5];
      float x02 = Ki0[6]*c0.x + Ki0[7]*c0.y + Ki0[8];
      float x10 = Ki1[0]*c1.x + Ki1[1]*c1.y + Ki1[2];
      float x11 = Ki1[3]*c1.x + Ki1[4]*c1.y + Ki1[5];
      float x12 = Ki1[6]*c1.x + Ki1[7]*c1.y + Ki1[8];
      int n = tid + k*256;
      sP[n] = make_float4(x00, x01, x10, x11);
      sW[n] = cw;
      float s0a[6] = {x00*x00, x00*x01, x00*x02, x01*x01, x01*x02, x02*x02};
      float s1a[6] = {x10*x10, x10*x11, x10*x12, x11*x11, x11*x12, x12*x12};
      float ws1[6];
      #pragma unroll
      for (int a=0;a<6;a++) ws1[a] = cw*s1a[a];
      #pragma unroll
      for (int a=0;a<6;a++)
        #pragma unroll
        for (int bb2=0;bb2<6;bb2++)
          acc[a*6+bb2] = fmaf(ws1[a], s0a[bb2], acc[a*6+bb2]);
      c0 = d0; c1 = d1; cw = dw;
      d0 = n0; d1 = n1; dw = nw;
    }
    #pragma unroll
    for (int i=0;i<36;i++) {
      acc[i] += __shfl_down_sync(0xffffffffu, acc[i], 16);
      acc[i] += __shfl_down_sync(0xffffffffu, acc[i], 8);
      acc[i] += __shfl_down_sync(0xffffffffu, acc[i], 4);
      acc[i] += __shfl_down_sync(0xffffffffu, acc[i], 2);
      acc[i] += __shfl_down_sync(0xffffffffu, acc[i], 1);
    }
    if (lane == 0) {
      #pragma unroll
      for (int i=0;i<36;i++) sred[warp][i] = acc[i];
    }
    __syncthreads();
    if (tid < 36) {
      float s = 0.f;
      #pragma unroll
      for (int wp=0; wp<8; wp++) s += sred[wp][tid];
      sT[tid] = s;
    }
    __syncthreads();
  }

  // ---- phase 2: eigensolve + essential decomposition (warp 0) ----
  if (warp == 0) {
    float* A = (float*)&sd[0];
    float* V = ((float*)&sd[0]) + 81;

    if (lane < 9) {
      const int i0 = lane / 3, j0 = lane % 3;
      #pragma unroll
      for (int j = 0; j < 9; j++) {
        int k0 = j / 3, l0 = j % 3;
        A[lane*9+j] = sT[p2i(i0,k0)*6 + p2i(j0,l0)];
        V[lane*9+j] = (lane==j) ? 1.0f : 0.0f;
      }
    }
    __syncwarp();

    // Phase A: parallel-ordered fp32 Jacobi, 4 sweeps
    for (int sweep = 0; sweep < 4; sweep++) {
      for (int r = 0; r < 9; r++) {
        const int bye = (5 * ((2*r) % 9)) % 9;
        if (lane < 4) {
          int d = lane + 1;
          int a = (bye + d) % 9;
          int bq = (bye + 9 - d) % 9;
          int p = a < bq ? a : bq;
          int q = a < bq ? bq : a;
          float apq = A[p*9+q], app = A[p*9+p], aqq = A[q*9+q];
          float c = 1.0f, s = 0.0f;
          if (fabsf(apq) > 6e-8f * (fabsf(app) + fabsf(aqq))) {
            float tau = __fdividef(aqq - app, 2.0f * apq);
            float t = ((tau >= 0.0f) ? 1.0f : -1.0f) / (fabsf(tau) + sqrtf(1.0f + tau*tau));
            c = rsqrtf(1.0f + t*t);
            s = t * c;
          }
          scs[lane] = c; sss[lane] = s;
        }
        __syncwarp();
        float cr[4], sr[4];
        int pr[4], qr[4];
        #pragma unroll
        for (int d = 0; d < 4; d++) {
          cr[d] = scs[d]; sr[d] = sss[d];
          int a = (bye + d + 1) % 9;
          int bq = (bye + 8 - d) % 9;
          pr[d] = a < bq ? a : bq;
          qr[d] = a < bq ? bq : a;
        }
        if (lane < 9) {
          #pragma unroll
          for (int d = 0; d < 4; d++) {
            int p = pr[d], q = qr[d];
            float vp = A[lane*9+p], vq = A[lane*9+q];
            A[lane*9+p] = cr[d]*vp - sr[d]*vq;
            A[lane*9+q] = sr[d]*vp + cr[d]*vq;
            float wp = V[lane*9+p], wq = V[lane*9+q];
            V[lane*9+p] = cr[d]*wp - sr[d]*wq;
            V[lane*9+q] = sr[d]*wp + cr[d]*wq;
          }
        }
        __syncwarp();
        if (lane < 9) {
          #pragma unroll
          for (int d = 0; d < 4; d++) {
            int p = pr[d], q = qr[d];
            float vp = A[p*9+lane], vq = A[q*9+lane];
            A[p*9+lane] = cr[d]*vp - sr[d]*vq;
            A[q*9+lane] = sr[d]*vp + cr[d]*vq;
          }
        }
        __syncwarp();
      }
    }

    // sigma + seed (before overwriting A/V with D)
    if (lane == 0) {
      int mi = 0; float mv = A[0];
      #pragma unroll
      for (int k=1;k<9;k++){ float dv=A[k*9+k]; if (dv<mv){mv=dv;mi=k;} }
      sMi = mi; sSigma = (double)mv;
    }
    __syncwarp();
    {
      int mi = sMi;
      if (lane < 9) sx[lane] = (double)V[lane*9+mi];
    }
    double sigma = sSigma;
    __syncwarp();

    // build D = M - sigma*I in parallel (overwrite A/V region)
    double* D = &sd[0];
    if (lane < 9) {
      int i0 = lane/3, j0 = lane%3;
      #pragma unroll
      for (int j=0;j<9;j++) {
        int k0 = j/3, l0 = j%3;
        D[lane*9+j] = (double)sT[p2i(i0,k0)*6 + p2i(j0,l0)];
      }
      D[lane*9+lane] -= sigma;
    }
    __syncwarp();

    // parallel LU with partial pivoting (rows across lanes)
    for (int k=0;k<9;k++) {
      if (lane == 0) {
        int p = k; double mx = fabs(D[k*9+k]);
        for (int i=k+1;i<9;i++){ double v = fabs(D[i*9+k]); if (v > mx){ mx=v; p=i; } }
        sIpiv[k] = p;
      }
      __syncwarp();
      int p = sIpiv[k];
      if (p != k && lane < 9) {
        double t = D[k*9+lane]; D[k*9+lane] = D[p*9+lane]; D[p*9+lane] = t;
      }
      __syncwarp();
      double pv = D[k*9+k];
      if (fabs(pv) < 1e-30) pv = (pv >= 0.0) ? 1e-30 : -1e-30;
      double ipv = drecip(pv);
      if (lane == 0) sDinv[k] = ipv;
      if (lane > k && lane < 9) {
        double l = D[lane*9+k] * ipv;
        D[lane*9+k] = l;
        for (int j=k+1;j<9;j++) D[lane*9+j] -= l * D[k*9+j];
      }
      __syncwarp();
    }

    // lane 0: inverse-iteration solves + 3x3 SVD
    if (lane == 0) {
      double x[9], Dinv[9];
      int ipiv[9];
      #pragma unroll
      for (int k=0;k<9;k++){ x[k]=sx[k]; Dinv[k]=sDinv[k]; ipiv[k]=sIpiv[k]; }

      for (int it=0; it<2; it++) {
        for (int k=0;k<9;k++){ int p=ipiv[k]; if (p!=k){ double t=x[k]; x[k]=x[p]; x[p]=t; } }
        for (int i=1;i<9;i++){ double s=x[i]; for (int j=0;j<i;j++) s -= D[i*9+j]*x[j]; x[i]=s; }
        for (int i=8;i>=0;i--){ double s=x[i]; for (int j=i+1;j<9;j++) s -= D[i*9+j]*x[j]; x[i]=s*Dinv[i]; }
        double nn = 0.0;
        for (int k=0;k<9;k++) nn += x[k]*x[k];
        double innn = drsqrt(nn);
        for (int k=0;k<9;k++) x[k] *= innn;
      }

      double e[9];
      #pragma unroll
      for (int k=0;k<9;k++) e[k] = x[k];

      double G3[3][3];
      #pragma unroll
      for (int i=0;i<3;i++)
        #pragma unroll
        for (int j=0;j<3;j++)
          G3[i][j] = e[0+i]*e[0+j] + e[3+i]*e[3+j] + e[6+i]*e[6+j];

      double Qm[3][3] = {{1,0,0},{0,1,0},{0,0,1}};
      #pragma unroll
      for (int sw=0; sw<3; sw++) { rot3d<0,1>(G3,Qm); rot3d<0,2>(G3,Qm); rot3d<1,2>(G3,Qm); }

      double lam0=G3[0][0], lam1=G3[1][1], lam2=G3[2][2];
      int o0, o1, o2;
      if (lam0 >= lam1) {
        if (lam0 >= lam2) { o0=0; if (lam1>=lam2){o1=1;o2=2;} else {o1=2;o2=1;} }
        else              { o0=2; o1=0; o2=1; }
      } else {
        if (lam1 >= lam2) { o0=1; if (lam0>=lam2){o1=0;o2=2;} else {o1=2;o2=0;} }
        else              { o0=2; o1=1; o2=0; }
      }
      double v1[3] = {Qm[0][o0], Qm[1][o0], Qm[2][o0]};
      double v2[3] = {Qm[0][o1], Qm[1][o1], Qm[2][o1]};
      double v3[3] = {Qm[0][o2], Qm[1][o2], Qm[2][o2]};

      double u1[3], u2[3], u3[3];
      #pragma unroll
      for (int i=0;i<3;i++) {
        u1[i] = e[3*i+0]*v1[0] + e[3*i+1]*v1[1] + e[3*i+2]*v1[2];
        u2[i] = e[3*i+0]*v2[0] + e[3*i+1]*v2[1] + e[3*i+2]*v2[2];
      }
      double in1 = drsqrt(fmax(u1[0]*u1[0]+u1[1]*u1[1]+u1[2]*u1[2], 1e-300));
      double in2 = drsqrt(fmax(u2[0]*u2[0]+u2[1]*u2[1]+u2[2]*u2[2], 1e-300));
      #pragma unroll
      for (int i=0;i<3;i++){ u1[i]*=in1; u2[i]*=in2; }
      u3[0] = u1[1]*u2[2] - u1[2]*u2[1];
      u3[1] = u1[2]*u2[0] - u1[0]*u2[2];
      u3[2] = u1[0]*u2[1] - u1[1]*u2[0];
      double in3 = drsqrt(fmax(u3[0]*u3[0]+u3[1]*u3[1]+u3[2]*u3[2], 1e-300));
      #pragma unroll
      for (int i=0;i<3;i++) u3[i]*=in3;

      // det(R1) = det(R2) = det(U)*det(V)  (column swap + negation cancel)
      double detU = u1[0]*(u2[1]*u3[2]-u2[2]*u3[1])
                  - u1[1]*(u2[0]*u3[2]-u2[2]*u3[0])
                  + u1[2]*(u2[0]*u3[1]-u2[1]*u3[0]);
      double detV = v1[0]*(v2[1]*v3[2]-v2[2]*v3[1])
                  - v1[1]*(v2[0]*v3[2]-v2[2]*v3[0])
                  + v1[2]*(v2[0]*v3[1]-v2[1]*v3[0]);
      double dd = detU * detV;
      sSgn = (dd > 0.0) ? 1.0 : ((dd < 0.0) ? -1.0 : 0.0);
      #pragma unroll
      for (int i=0;i<3;i++) {
        sUV[i]    = u1[i];
        sUV[3+i]  = u2[i];
        sUV[6+i]  = u3[i];
        sUV[9+i]  = v1[i];
        sUV[12+i] = v2[i];
        sUV[15+i] = v3[i];
        st3[i] = (float)u3[i];
      }
    }
    __syncwarp();

    // parallel R1/R2 build (one element per lane)
    if (lane < 9) {
      int i = lane / 3, j = lane % 3;
      double u1i = sUV[i], u2i = sUV[3+i], u3i = sUV[6+i];
      double v1j = sUV[9+j], v2j = sUV[12+j], v3j = sUV[15+j];
      double sg = sSgn;
      double r1 =  u2i*v1j - u1i*v2j + u3i*v3j;
      double r2 = -u2i*v1j + u1i*v2j + u3i*v3j;
      sR1[lane] = (float)(r1*sg);
      sR2[lane] = (float)(r2*sg);
    }
  }
  __syncthreads();

  // ---- phase 3: cheirality (division-free sign tests) ----
  float R1[9], R2[9];
  #pragma unroll
  for (int i=0;i<9;i++){ R1[i]=sR1[i]; R2[i]=sR2[i]; }
  const float tv0=st3[0], tv1=st3[1], tv2=st3[2];

  float sc0=0.f, sc1=0.f, sc2=0.f, sc3=0.f;
  if (affine) {
    #pragma unroll
    for (int k = 0; k < NPTS/256; k++) {
      int n = tid + k*256;
      float4 q = sP[n];
      float w = sW[n];
      float bb = q.z*q.z + q.w*q.w + 1.0f;
      float bt = q.z*tv0 + q.w*tv1 + tv2;
      {
        float a0 = R1[0]*q.x + R1[1]*q.y + R1[2];
        float a1 = R1[3]*q.x + R1[4]*q.y + R1[5];
        float a2 = R1[6]*q.x + R1[7]*q.y + R1[8];
        float aa = a0*a0 + a1*a1 + a2*a2;
        float ab = a0*q.z + a1*q.w + a2;
        float at = a0*tv0 + a1*tv1 + a2*tv2;
        float det = aa*bb - ab*ab + 1e-9f;
        float n0 = -at*bb + ab*bt;
        float n1 = aa*bt - ab*at;
        bool dp = det >= 0.f;
        if (dp ? (n0 > 0.f && n1 > 0.f) : (n0 < 0.f && n1 < 0.f)) sc0 += w;
        if (dp ? (n0 < 0.f && n1 < 0.f) : (n0 > 0.f && n1 > 0.f)) sc1 += w;
      }
      {
        float a0 = R2[0]*q.x + R2[1]*q.y + R2[2];
        float a1 = R2[3]*q.x + R2[4]*q.y + R2[5];
        float a2 = R2[6]*q.x + R2[7]*q.y + R2[8];
        float aa = a0*a0 + a1*a1 + a2*a2;
        float ab = a0*q.z + a1*q.w + a2;
        float at = a0*tv0 + a1*tv1 + a2*tv2;
        float det = aa*bb - ab*ab + 1e-9f;
        float n0 = -at*bb + ab*bt;
        float n1 = aa*bt - ab*at;
        bool dp = det >= 0.f;
        if (dp ? (n0 > 0.f && n1 > 0.f) : (n0 < 0.f && n1 < 0.f)) sc2 += w;
        if (dp ? (n0 < 0.f && n1 < 0.f) : (n0 > 0.f && n1 > 0.f)) sc3 += w;
      }
    }
  } else {
    #pragma unroll
    for (int k = 0; k < NPTS/256; k++) {
      int n = tid + k*256;
      float2 p0 = kp0[n]; float2 p1 = kp1[n]; float w = wv[n];
      float x00 = Ki0[0]*p0.x + Ki0[1]*p0.y + Ki0[2];
      float x01 = Ki0[3]*p0.x + Ki0[4]*p0.y + Ki0[5];
      float x02 = Ki0[6]*p0.x + Ki0[7]*p0.y + Ki0[8];
      float x10 = Ki1[0]*p1.x + Ki1[1]*p1.y + Ki1[2];
      float x11 = Ki1[3]*p1.x + Ki1[4]*p1.y + Ki1[5];
      float x12 = Ki1[6]*p1.x + Ki1[7]*p1.y + Ki1[8];
      float bb = x10*x10 + x11*x11 + x12*x12;
      float bt = x10*tv0 + x11*tv1 + x12*tv2;
      {
        float a0 = R1[0]*x00 + R1[1]*x01 + R1[2]*x02;
        float a1 = R1[3]*x00 + R1[4]*x01 + R1[5]*x02;
        float a2 = R1[6]*x00 + R1[7]*x01 + R1[8]*x02;
        float aa = a0*a0 + a1*a1 + a2*a2;
        float ab = a0*x10 + a1*x11 + a2*x12;
        float at = a0*tv0 + a1*tv1 + a2*tv2;
        float det = aa*bb - ab*ab + 1e-9f;
        float n0 = -at*bb + ab*bt;
        float n1 = aa*bt - ab*at;
        bool dp = det >= 0.f;
        if (dp ? (n0 > 0.f && n1 > 0.f) : (n0 < 0.f && n1 < 0.f)) sc0 += w;
        if (dp ? (n0 < 0.f && n1 < 0.f) : (n0 > 0.f && n1 > 0.f)) sc1 += w;
      }
      {
        float a0 = R2[0]*x00 + R2[1]*x01 + R2[2]*x02;
        float a1 = R2[3]*x00 + R2[4]*x01 + R2[5]*x02;
        float a2 = R2[6]*x00 + R2[7]*x01 + R2[8]*x02;
        float aa = a0*a0 + a1*a1 + a2*a2;
        float ab = a0*x10 + a1*x11 + a2*x12;
        float at = a0*tv0 + a1*tv1 + a2*tv2;
        float det = aa*bb - ab*ab + 1e-9f;
        float n0 = -at*bb + ab*bt;
        float n1 = aa*bt - ab*at;
        bool dp = det >= 0.f;
        if (dp ? (n0 > 0.f && n1 > 0.f) : (n0 < 0.f && n1 < 0.f)) sc2 += w;
        if (dp ? (n0 < 0.f && n1 < 0.f) : (n0 > 0.f && n1 > 0.f)) sc3 += w;
      }
    }
  }
  #pragma unroll
  for (int off=16; off; off>>=1) {
    sc0 += __shfl_down_sync(0xffffffffu, sc0, off);
    sc1 += __shfl_down_sync(0xffffffffu, sc1, off);
    sc2 += __shfl_down_sync(0xffffffffu, sc2, off);
    sc3 += __shfl_down_sync(0xffffffffu, sc3, off);
  }
  if (lane == 0) { sred[warp][0]=sc0; sred[warp][1]=sc1; sred[warp][2]=sc2; sred[warp][3]=sc3; }
  __syncthreads();
  if (tid == 0) {
    float s0=0.f, s1=0.f, s2=0.f, s3=0.f;
    #pragma unroll
    for (int wp=0; wp<8; wp++){ s0+=sred[wp][0]; s1+=sred[wp][1]; s2+=sred[wp][2]; s3+=sred[wp][3]; }
    float bs = s0; int bi = 0;
    if (s1 > bs){ bs=s1; bi=1; }
    if (s2 > bs){ bs=s2; bi=2; }
    if (s3 > bs){ bs=s3; bi=3; }
    const float* R = (bi < 2) ? sR1 : sR2;
    float sgn = (bi & 1) ? -1.f : 1.f;
    float ts = tscale[b*2];
    float t0 = (sgn*st3[0])*ts;
    float t1 = (sgn*st3[1])*ts;
    float t2 = (sgn*st3[2])*ts;
    float* o = out + (size_t)b*32;
    o[0]=R[0]; o[1]=R[1]; o[2]=R[2];  o[3]=t0;
    o[4]=R[3]; o[5]=R[4]; o[6]=R[5];  o[7]=t1;
    o[8]=R[6]; o[9]=R[7]; o[10]=R[8]; o[11]=t2;
    o[12]=0.f; o[13]=0.f; o[14]=0.f; o[15]=1.f;
    float ti0 = -(R[0]*t0 + R[3]*t1 + R[6]*t2);
    float ti1 = -(R[1]*t0 + R[4]*t1 + R[7]*t2);
    float ti2 = -(R[2]*t0 + R[5]*t1 + R[8]*t2);
    o[16]=R[0]; o[17]=R[3]; o[18]=R[6]; o[19]=ti0;
    o[20]=R[1]; o[21]=R[4]; o[22]=R[7]; o[23]=ti1;
    o[24]=R[2]; o[25]=R[5]; o[26]=R[8]; o[27]=ti2;
    o[28]=0.f; o[29]=0.f; o[30]=0.f; o[31]=1.f;
  }
}

extern "C" void kernel_launch(void* const* d_in, const int* in_sizes, int n_in,
                              void* d_out, int out_size) {
  const float* kpts0  = (const float*)d_in[0];
  const float* kpts1  = (const float*)d_in[1];
  const float* conf   = (const float*)d_in[2];
  const float* tscale = (const float*)d_in[3];
  const float* Kmat   = (const float*)d_in[4];
  float* out = (float*)d_out;

  cudaFuncSetAttribute(k_fused, cudaFuncAttributeMaxDynamicSharedMemorySize, DYN_SMEM);
  k_fused<<<BATCH, 256, DYN_SMEM>>>(kpts0, kpts1, conf, tscale, Kmat, out);
}